// round 8
// baseline (speedup 1.0000x reference)
#include <cuda_runtime.h>
#include <math.h>

#define NPTS 2048
#define DIN  768
#define DOUT 64
#define NMAT 5
#define LN_N   7.624618986159398f      // ln(2048)
#define LOG2E  1.4426950408889634f
#define LN2    0.6931471805599453f
#define NSTEP  48                      // 47 scan steps + 1 final
#define GRID_SOLVE 112                 // 5*16 row blocks + 2*16 col blocks

// ---------------------------------------------------------------------------
// Device scratch (static globals — no allocation in kernel_launch)
// ---------------------------------------------------------------------------
__device__ __align__(16) float d_Wt[DIN * DOUT];             // W^T: [768][64]
__device__ __align__(16) float d_P[3][NPTS * DOUT];          // pd, p1, p2
__device__ __align__(16) float d_SQ[3][NPTS];                // 0.5*||row||^2
__device__ __align__(16) float d_C[NMAT][(size_t)NPTS * NPTS];
// 0:Cxx 1:C11 2:C22 3:Cxy1 4:Cxy2
__device__ __align__(16) float d_pot[2][7][NPTS];            // ping-pong potentials
// slots: 0:f_xx 1:f_11 2:f_22 3:f_xy1 4:g_xy1 5:f_xy2 6:g_xy2
__device__ __align__(16) float d_potF[7][NPTS];              // final potentials
__device__ unsigned g_bar;                                   // grid barrier counter

__constant__ int cAi[5] = {0, 1, 2, 0, 0};
__constant__ int cBi[5] = {0, 1, 2, 1, 2};
// pass -> (matrix, vin slot, out slot); passes 5,6 are column-mode
__constant__ int cMat[7] = {0, 1, 2, 3, 4, 3, 4};
__constant__ int cVin[7] = {0, 1, 2, 4, 6, 3, 5};
__constant__ int cOut[7] = {0, 1, 2, 3, 5, 4, 6};

struct Sched { float eps[NSTEP]; };

__device__ __forceinline__ float ex2f(float x) {
    float r; asm("ex2.approx.ftz.f32 %0, %1;" : "=f"(r) : "f"(x)); return r;
}
__device__ __forceinline__ float lg2f(float x) {
    float r; asm("lg2.approx.f32 %0, %1;" : "=f"(r) : "f"(x)); return r;
}

// grid barrier: all GRID_SOLVE blocks are co-resident (grid <= #SMs, 1 block
// always fits an SM), so an atomic+spin barrier cannot deadlock.
__device__ __forceinline__ void gridbar(unsigned target) {
    __syncthreads();
    if (threadIdx.x == 0) {
        __threadfence();
        atomicAdd(&g_bar, 1u);
        unsigned v;
        do {
            asm volatile("ld.global.acquire.gpu.u32 %0, [%1];"
                         : "=r"(v) : "l"(&g_bar));
            if (v < target) __nanosleep(64);
        } while (v < target);
    }
    __syncthreads();
}

// ---------------------------------------------------------------------------
// W transpose:  Wt[j][k] = W[k][j]
// ---------------------------------------------------------------------------
__global__ void k_transposeW(const float* __restrict__ W) {
    int e = blockIdx.x * blockDim.x + threadIdx.x;
    if (e < DIN * DOUT) {
        int j = e / DOUT, k = e % DOUT;
        d_Wt[e] = W[k * DIN + j];
    }
}

// ---------------------------------------------------------------------------
// predict: P = relu(X @ W^T + b). 64x64 tile / 256 threads.
// ---------------------------------------------------------------------------
__global__ __launch_bounds__(256) void k_predict(const float* __restrict__ X0,
                                                 const float* __restrict__ X1,
                                                 const float* __restrict__ X2,
                                                 const float* __restrict__ bias) {
    __shared__ __align__(16) float Xs[64 * 68];   // [kk][row]
    __shared__ __align__(16) float Ws[64 * 64];   // [kk][col]
    const float* X = (blockIdx.y == 0) ? X0 : (blockIdx.y == 1) ? X1 : X2;
    int rowBase = blockIdx.x * 64;
    int tid = threadIdx.x;
    int ty = tid >> 4, tx = tid & 15;

    float acc[4][4];
#pragma unroll
    for (int i = 0; i < 4; i++)
#pragma unroll
        for (int j = 0; j < 4; j++) acc[i][j] = 0.f;

    for (int k0 = 0; k0 < DIN; k0 += 64) {
#pragma unroll
        for (int i = 0; i < 16; i++) {
            int e = tid + i * 256;
            int r = e >> 6, c = e & 63;
            Xs[c * 68 + r] = X[(size_t)(rowBase + r) * DIN + k0 + c];
            Ws[r * 64 + c] = d_Wt[(k0 + r) * DOUT + c];
        }
        __syncthreads();
#pragma unroll
        for (int kk = 0; kk < 64; kk++) {
            float4 a = *reinterpret_cast<const float4*>(&Xs[kk * 68 + ty * 4]);
            float4 b = *reinterpret_cast<const float4*>(&Ws[kk * 64 + tx * 4]);
            float av[4] = {a.x, a.y, a.z, a.w};
            float bv[4] = {b.x, b.y, b.z, b.w};
#pragma unroll
            for (int i = 0; i < 4; i++)
#pragma unroll
                for (int j = 0; j < 4; j++) acc[i][j] = fmaf(av[i], bv[j], acc[i][j]);
        }
        __syncthreads();
    }

#pragma unroll
    for (int i = 0; i < 4; i++)
#pragma unroll
        for (int j = 0; j < 4; j++) {
            float v = acc[i][j] + bias[tx * 4 + j];
            v = fmaxf(v, 0.f);
            d_P[blockIdx.y][(rowBase + ty * 4 + i) * DOUT + tx * 4 + j] = v;
        }
}

// ---------------------------------------------------------------------------
// 0.5 * ||row||^2, one warp per row
// ---------------------------------------------------------------------------
__global__ void k_sqnorm() {
    int wid = threadIdx.x >> 5, lane = threadIdx.x & 31;
    int grow = blockIdx.x * 8 + wid;
    int b = grow >> 11, r = grow & (NPTS - 1);
    float v0 = d_P[b][r * DOUT + lane];
    float v1 = d_P[b][r * DOUT + 32 + lane];
    float v = v0 * v0 + v1 * v1;
#pragma unroll
    for (int off = 16; off > 0; off >>= 1)
        v += __shfl_xor_sync(0xffffffffu, v, off);
    if (lane == 0) d_SQ[b][r] = 0.5f * v;
}

// ---------------------------------------------------------------------------
// cost: C[i][j] = 0.5||a_i||^2 + 0.5||b_j||^2 - a_i . b_j  (K=64)
// 128x128 tile per block, 8x8 per thread (16 FMA per LDS.128 -> FMA-bound).
// ---------------------------------------------------------------------------
__global__ __launch_bounds__(256) void k_cost() {
    __shared__ __align__(16) float sA[16][136];   // [kk][row], padded
    __shared__ __align__(16) float sB[16][136];   // [kk][col]
    const int z = blockIdx.z;
    const int ai = cAi[z], bi = cBi[z];
    const float* A = d_P[ai];
    const float* B = d_P[bi];
    const int i0 = blockIdx.y * 128, j0 = blockIdx.x * 128;
    const int tid = threadIdx.x;
    const int ty = tid >> 4, tx = tid & 15;

    float acc[8][8];
#pragma unroll
    for (int i = 0; i < 8; i++)
#pragma unroll
        for (int j = 0; j < 8; j++) acc[i][j] = 0.f;

    const int lr = tid >> 1;              // 0..127 (row within tile)
    const int lh = (tid & 1) * 8;         // 0 or 8 (k-half within chunk)

    for (int k0 = 0; k0 < DOUT; k0 += 16) {
        {
            float4 v0 = *reinterpret_cast<const float4*>(
                A + (size_t)(i0 + lr) * DOUT + k0 + lh);
            float4 v1 = *reinterpret_cast<const float4*>(
                A + (size_t)(i0 + lr) * DOUT + k0 + lh + 4);
            sA[lh + 0][lr] = v0.x; sA[lh + 1][lr] = v0.y;
            sA[lh + 2][lr] = v0.z; sA[lh + 3][lr] = v0.w;
            sA[lh + 4][lr] = v1.x; sA[lh + 5][lr] = v1.y;
            sA[lh + 6][lr] = v1.z; sA[lh + 7][lr] = v1.w;
            float4 w0 = *reinterpret_cast<const float4*>(
                B + (size_t)(j0 + lr) * DOUT + k0 + lh);
            float4 w1 = *reinterpret_cast<const float4*>(
                B + (size_t)(j0 + lr) * DOUT + k0 + lh + 4);
            sB[lh + 0][lr] = w0.x; sB[lh + 1][lr] = w0.y;
            sB[lh + 2][lr] = w0.z; sB[lh + 3][lr] = w0.w;
            sB[lh + 4][lr] = w1.x; sB[lh + 5][lr] = w1.y;
            sB[lh + 6][lr] = w1.z; sB[lh + 7][lr] = w1.w;
        }
        __syncthreads();
#pragma unroll
        for (int kk = 0; kk < 16; kk++) {
            float4 a0 = *reinterpret_cast<const float4*>(&sA[kk][ty * 8]);
            float4 a1 = *reinterpret_cast<const float4*>(&sA[kk][ty * 8 + 4]);
            float4 b0 = *reinterpret_cast<const float4*>(&sB[kk][tx * 8]);
            float4 b1 = *reinterpret_cast<const float4*>(&sB[kk][tx * 8 + 4]);
            float av[8] = {a0.x, a0.y, a0.z, a0.w, a1.x, a1.y, a1.z, a1.w};
            float bv[8] = {b0.x, b0.y, b0.z, b0.w, b1.x, b1.y, b1.z, b1.w};
#pragma unroll
            for (int i = 0; i < 8; i++)
#pragma unroll
                for (int j = 0; j < 8; j++)
                    acc[i][j] = fmaf(av[i], bv[j], acc[i][j]);
        }
        __syncthreads();
    }

    float sqa[8], sqb[8];
#pragma unroll
    for (int i = 0; i < 8; i++) sqa[i] = d_SQ[ai][i0 + ty * 8 + i];
#pragma unroll
    for (int j = 0; j < 8; j++) sqb[j] = d_SQ[bi][j0 + tx * 8 + j];

    float* Cm = d_C[z];
#pragma unroll
    for (int i = 0; i < 8; i++) {
        float4 o0, o1;
        o0.x = sqa[i] + sqb[0] - acc[i][0];
        o0.y = sqa[i] + sqb[1] - acc[i][1];
        o0.z = sqa[i] + sqb[2] - acc[i][2];
        o0.w = sqa[i] + sqb[3] - acc[i][3];
        o1.x = sqa[i] + sqb[4] - acc[i][4];
        o1.y = sqa[i] + sqb[5] - acc[i][5];
        o1.z = sqa[i] + sqb[6] - acc[i][6];
        o1.w = sqa[i] + sqb[7] - acc[i][7];
        float* dst = Cm + (size_t)(i0 + ty * 8 + i) * NPTS + j0 + tx * 8;
        *reinterpret_cast<float4*>(dst) = o0;
        *reinterpret_cast<float4*>(dst + 4) = o1;
    }
}

// ---------------------------------------------------------------------------
// zero ping-pong potential buffers + barrier counter
// ---------------------------------------------------------------------------
__global__ void k_init() {
    int e = blockIdx.x * blockDim.x + threadIdx.x;
    if (e < 2 * 7 * NPTS) (&d_pot[0][0][0])[e] = 0.f;
    if (e == 0) g_bar = 0u;
}

// ---------------------------------------------------------------------------
// Persistent Sinkhorn solver: all 48 steps in one kernel, software grid
// barrier between steps. 112 blocks, each handles one 128-row (passes 0-4)
// or 128-col (passes 5,6) slab of one matrix, 1 MB of reads per step.
// f_i = eps*(ln N - ln2 * LSE2_j[(vin_j - C_ij)*log2e/eps])
// Cross-step potentials go through L2 only (__ldcg/__stcg) — L1 is not
// coherent across blocks.
// ---------------------------------------------------------------------------
__global__ __launch_bounds__(256) void k_solve(Sched sc, float* __restrict__ outp) {
    __shared__ __align__(16) float sg[NPTS];
    __shared__ __align__(16) float4 wm[8][32];
    __shared__ __align__(16) float4 ws[8][32];

    const int blk = blockIdx.x;
    const bool isRow = (blk < 80);
    const int pass = isRow ? (blk >> 4) : (5 + ((blk - 80) >> 4));
    const int sub  = isRow ? (blk & 15) : ((blk - 80) & 15);
    const int vinSlot = cVin[pass], outSlot = cOut[pass];
    const float* __restrict__ Cm = d_C[cMat[pass]];
    const int wid = threadIdx.x >> 5, lane = threadIdx.x & 31;

    for (int it = 0; it < NSTEP; ++it) {
        const int cur = it & 1;
        const float eps = sc.eps[it];
        const bool avg = (it < NSTEP - 1);
        const float pscale = LOG2E / eps;
        const float nscale = -pscale;
        const float* vin  = d_pot[cur][vinSlot];
        const float* favg = d_pot[cur][outSlot];
        float* out = avg ? d_pot[cur ^ 1][outSlot] : d_potF[outSlot];

        // stage vin * log2e/eps into shared (L2 reads)
        for (int j = threadIdx.x; j < NPTS; j += 256)
            sg[j] = __ldcg(vin + j) * pscale;
        __syncthreads();

        if (isRow) {
            const float4* sg4 = reinterpret_cast<const float4*>(sg);
#pragma unroll 1
            for (int r = 0; r < 16; ++r) {
                const int row = sub * 128 + wid * 16 + r;
                const float4* __restrict__ Crow4 =
                    reinterpret_cast<const float4*>(Cm + (size_t)row * NPTS);
                float4 xv[8];
                float m1 = -3.4e38f;
#pragma unroll
                for (int k = 0; k < 8; k++) {
                    float4 c = Crow4[k * 32 + lane];
                    float4 g = sg4[k * 32 + lane];
                    float4 t;
                    t.x = fmaf(c.x, nscale, g.x);
                    t.y = fmaf(c.y, nscale, g.y);
                    t.z = fmaf(c.z, nscale, g.z);
                    t.w = fmaf(c.w, nscale, g.w);
                    xv[k] = t;
                    m1 = fmaxf(m1, fmaxf(fmaxf(t.x, t.y), fmaxf(t.z, t.w)));
                }
                float s1 = 0.f;
#pragma unroll
                for (int k = 0; k < 8; k++)
                    s1 += ex2f(xv[k].x - m1) + ex2f(xv[k].y - m1)
                        + ex2f(xv[k].z - m1) + ex2f(xv[k].w - m1);

                float m2 = -3.4e38f;
#pragma unroll
                for (int k = 0; k < 8; k++) {
                    float4 c = Crow4[256 + k * 32 + lane];
                    float4 g = sg4[256 + k * 32 + lane];
                    float4 t;
                    t.x = fmaf(c.x, nscale, g.x);
                    t.y = fmaf(c.y, nscale, g.y);
                    t.z = fmaf(c.z, nscale, g.z);
                    t.w = fmaf(c.w, nscale, g.w);
                    xv[k] = t;
                    m2 = fmaxf(m2, fmaxf(fmaxf(t.x, t.y), fmaxf(t.z, t.w)));
                }
                float s2 = 0.f;
#pragma unroll
                for (int k = 0; k < 8; k++)
                    s2 += ex2f(xv[k].x - m2) + ex2f(xv[k].y - m2)
                        + ex2f(xv[k].z - m2) + ex2f(xv[k].w - m2);

                float m = fmaxf(m1, m2);
                float s = s1 * ex2f(m1 - m) + s2 * ex2f(m2 - m);
#pragma unroll
                for (int off = 16; off > 0; off >>= 1) {
                    float mo = __shfl_xor_sync(0xffffffffu, m, off);
                    float so = __shfl_xor_sync(0xffffffffu, s, off);
                    float mn = fmaxf(m, mo);
                    s = s * ex2f(m - mn) + so * ex2f(mo - mn);
                    m = mn;
                }
                if (lane == 0) {
                    float ft = eps * (LN_N - (m + lg2f(s)) * LN2);
                    if (avg) ft = 0.5f * (__ldcg(favg + row) + ft);
                    __stcg(out + row, ft);
                }
            }
        } else {
            // column mode: lane owns 4 consecutive cols (float4 loads),
            // warp w covers rows [w*256, (w+1)*256)
            const int colg = sub * 128 + lane * 4;
            float4 m4 = make_float4(-3.4e38f, -3.4e38f, -3.4e38f, -3.4e38f);
            float4 s4 = make_float4(0.f, 0.f, 0.f, 0.f);
            const int rbase = wid * 256;
#pragma unroll 1
            for (int r0 = 0; r0 < 256; r0 += 8) {
                float4 t[8];
                float4 mc = make_float4(-3.4e38f, -3.4e38f, -3.4e38f, -3.4e38f);
#pragma unroll
                for (int k = 0; k < 8; k++) {
                    const int rr = rbase + r0 + k;
                    float4 c = *reinterpret_cast<const float4*>(
                        Cm + (size_t)rr * NPTS + colg);
                    float sv = sg[rr];
                    float4 tt;
                    tt.x = fmaf(c.x, nscale, sv);
                    tt.y = fmaf(c.y, nscale, sv);
                    tt.z = fmaf(c.z, nscale, sv);
                    tt.w = fmaf(c.w, nscale, sv);
                    t[k] = tt;
                    mc.x = fmaxf(mc.x, tt.x); mc.y = fmaxf(mc.y, tt.y);
                    mc.z = fmaxf(mc.z, tt.z); mc.w = fmaxf(mc.w, tt.w);
                }
                float4 mn;
                mn.x = fmaxf(m4.x, mc.x); mn.y = fmaxf(m4.y, mc.y);
                mn.z = fmaxf(m4.z, mc.z); mn.w = fmaxf(m4.w, mc.w);
                s4.x *= ex2f(m4.x - mn.x); s4.y *= ex2f(m4.y - mn.y);
                s4.z *= ex2f(m4.z - mn.z); s4.w *= ex2f(m4.w - mn.w);
#pragma unroll
                for (int k = 0; k < 8; k++) {
                    s4.x += ex2f(t[k].x - mn.x);
                    s4.y += ex2f(t[k].y - mn.y);
                    s4.z += ex2f(t[k].z - mn.z);
                    s4.w += ex2f(t[k].w - mn.w);
                }
                m4 = mn;
            }
            wm[wid][lane] = m4;
            ws[wid][lane] = s4;
            __syncthreads();
            if (wid == 0) {
                float4 M = wm[0][lane], S = ws[0][lane];
#pragma unroll
                for (int w = 1; w < 8; w++) {
                    float4 mo = wm[w][lane], so = ws[w][lane];
                    float4 mn;
                    mn.x = fmaxf(M.x, mo.x); mn.y = fmaxf(M.y, mo.y);
                    mn.z = fmaxf(M.z, mo.z); mn.w = fmaxf(M.w, mo.w);
                    S.x = S.x * ex2f(M.x - mn.x) + so.x * ex2f(mo.x - mn.x);
                    S.y = S.y * ex2f(M.y - mn.y) + so.y * ex2f(mo.y - mn.y);
                    S.z = S.z * ex2f(M.z - mn.z) + so.z * ex2f(mo.z - mn.z);
                    S.w = S.w * ex2f(M.w - mn.w) + so.w * ex2f(mo.w - mn.w);
                    M = mn;
                }
                float4 g;
                g.x = eps * (LN_N - (M.x + lg2f(S.x)) * LN2);
                g.y = eps * (LN_N - (M.y + lg2f(S.y)) * LN2);
                g.z = eps * (LN_N - (M.z + lg2f(S.z)) * LN2);
                g.w = eps * (LN_N - (M.w + lg2f(S.w)) * LN2);
                if (avg) {
                    float4 fa = __ldcg(reinterpret_cast<const float4*>(favg + colg));
                    g.x = 0.5f * (fa.x + g.x);
                    g.y = 0.5f * (fa.y + g.y);
                    g.z = 0.5f * (fa.z + g.z);
                    g.w = 0.5f * (fa.w + g.w);
                }
                __stcg(reinterpret_cast<float4*>(out + colg), g);
            }
            __syncthreads();   // protect wm/ws before next step reuses them
        }

        gridbar((unsigned)GRID_SOLVE * (unsigned)(it + 1));
    }

    // final reduction in block 0
    if (blk == 0) {
        __shared__ float s1h[256], s2h[256];
        int t = threadIdx.x;
        float a1 = 0.f, a2 = 0.f;
        for (int i = t; i < NPTS; i += 256) {
            float fxx = __ldcg(&d_potF[0][i]);
            a1 += (__ldcg(&d_potF[3][i]) - fxx) + (__ldcg(&d_potF[4][i]) - __ldcg(&d_potF[1][i]));
            a2 += (__ldcg(&d_potF[5][i]) - fxx) + (__ldcg(&d_potF[6][i]) - __ldcg(&d_potF[2][i]));
        }
        s1h[t] = a1;
        s2h[t] = a2;
        __syncthreads();
        for (int off = 128; off > 0; off >>= 1) {
            if (t < off) { s1h[t] += s1h[t + off]; s2h[t] += s2h[t + off]; }
            __syncthreads();
        }
        if (t == 0) {
            const float inv = 1.0f / (float)NPTS;
            float dist1 = s1h[0] * inv;
            float dist2 = s2h[0] * inv;
            float z = 10.0f * (dist2 - dist1);
            outp[0] = 1.0f / (1.0f + expf(-z));
        }
    }
}

// ---------------------------------------------------------------------------
// Launcher (graph-capturable: kernel launches only)
// ---------------------------------------------------------------------------
extern "C" void kernel_launch(void* const* d_in, const int* in_sizes, int n_in,
                              void* d_out, int out_size) {
    (void)in_sizes; (void)n_in; (void)out_size;
    const float* dX = (const float*)d_in[0];
    const float* s1 = (const float*)d_in[1];
    const float* s2 = (const float*)d_in[2];
    const float* W  = (const float*)d_in[3];
    const float* bb = (const float*)d_in[4];
    float* out = (float*)d_out;

    k_transposeW<<<(DIN * DOUT + 255) / 256, 256>>>(W);
    k_predict<<<dim3(NPTS / 64, 3), 256>>>(dX, s1, s2, bb);
    k_sqnorm<<<3 * NPTS / 8, 256>>>();
    k_cost<<<dim3(16, 16, 5), 256>>>();
    k_init<<<(2 * 7 * NPTS + 255) / 256, 256>>>();

    // epsilon schedule (geomloss-style), computed in double, cast to float
    const double eps0 = 32.0;
    const double epsf = pow(0.05, 2.0);
    const double ratio = pow(0.9, 2.0);
    int n = (int)ceil(log(epsf / eps0) / log(ratio));   // 45
    Sched sc;
    int cnt = 0;
    for (int k = 0; k <= n; k++) {
        double v = eps0 * pow(ratio, (double)k);
        if (v < epsf) v = epsf;
        sc.eps[cnt++] = (float)v;
    }
    sc.eps[cnt++] = (float)epsf;        // index 46 (last scan step)
    sc.eps[cnt]   = (float)epsf;        // index 47 (final non-averaged step)

    k_solve<<<GRID_SOLVE, 256>>>(sc, out);
}